// round 9
// baseline (speedup 1.0000x reference)
#include <cuda_runtime.h>
#include <cuda_fp16.h>
#include <cstdint>

#define N_NODES 50000
#define N_EDGES 800000
#define F_IN    128
#define F_HID   128
#define F_OUT   64
#define SCAN_B  1024
#define SCAN_NB ((N_NODES + SCAN_B - 1) / SCAN_B)   // 49
#define GB1     ((N_NODES + 127) / 128)             // 391 gemm1 blocks
#define DEGB    ((N_EDGES + 255) / 256)             // 3125 deg blocks

// ---- zero-init region (single memset): [0,N)=deg_out [N,2N)=deg_in [2N,2N+64)=scan flags ----
#define A_DEGO  0
#define A_DEGI  N_NODES
#define A_FLAG  (2 * N_NODES)
#define A_PREF  (2 * N_NODES + 64)
#define A_TOTAL (2 * N_NODES + 128)
__device__ __align__(16) int    g_atomic[A_TOTAL];

__device__ __align__(16) __half g_z1h[N_NODES * F_HID];  // h@W1  fp16 [N,128]
__device__ __align__(16) __half g_z2h[N_NODES * F_OUT];  // h1@W2 fp16 [N,64]
__device__ __align__(16) float  g_norm_out[N_NODES];
__device__ __align__(16) float  g_norm_in [N_NODES];
__device__ __align__(16) int    g_row_start[N_NODES];
__device__ __align__(16) int    g_cursor[N_NODES];
__device__ __align__(16) int    g_csr_src[N_EDGES];

__device__ __forceinline__ int clampi(int v) {
    return v < 0 ? 0 : (v >= N_NODES ? N_NODES - 1 : v);
}

__device__ __forceinline__ uint32_t s2u(const void* p) {
    uint32_t a;
    asm("{ .reg .u64 t; cvta.to.shared.u64 t, %1; cvt.u32.u64 %0, t; }" : "=r"(a) : "l"(p));
    return a;
}

__device__ __forceinline__ void ldsm_x4(uint32_t& r0, uint32_t& r1, uint32_t& r2, uint32_t& r3, uint32_t addr) {
    asm volatile("ldmatrix.sync.aligned.m8n8.x4.shared.b16 {%0,%1,%2,%3}, [%4];"
                 : "=r"(r0), "=r"(r1), "=r"(r2), "=r"(r3) : "r"(addr));
}

__device__ __forceinline__ void ldsm_x4t(uint32_t& r0, uint32_t& r1, uint32_t& r2, uint32_t& r3, uint32_t addr) {
    asm volatile("ldmatrix.sync.aligned.m8n8.x4.trans.shared.b16 {%0,%1,%2,%3}, [%4];"
                 : "=r"(r0), "=r"(r1), "=r"(r2), "=r"(r3) : "r"(addr));
}

__device__ __forceinline__ void mma16816(float* c, const uint32_t* a, const uint32_t* b) {
    asm volatile("mma.sync.aligned.m16n8k16.row.col.f32.f16.f16.f32 "
                 "{%0,%1,%2,%3}, {%4,%5,%6,%7}, {%8,%9}, {%0,%1,%2,%3};"
                 : "+f"(c[0]), "+f"(c[1]), "+f"(c[2]), "+f"(c[3])
                 : "r"(a[0]), "r"(a[1]), "r"(a[2]), "r"(a[3]), "r"(b[0]), "r"(b[1]));
}

__device__ __forceinline__ uint4 f8_to_h8(float4 v0, float4 v1) {
    __half2 h0 = __floats2half2_rn(v0.x, v0.y);
    __half2 h1 = __floats2half2_rn(v0.z, v0.w);
    __half2 h2 = __floats2half2_rn(v1.x, v1.y);
    __half2 h3 = __floats2half2_rn(v1.z, v1.w);
    uint4 u;
    u.x = *(uint32_t*)&h0; u.y = *(uint32_t*)&h1;
    u.z = *(uint32_t*)&h2; u.w = *(uint32_t*)&h3;
    return u;
}

// ======= fused A: blocks [0,GB1) = GEMM1 (z1 = fp16(h@W1)); blocks [GB1,..) = degree histogram =======
__global__ __launch_bounds__(256) void k_fusedA(const float* __restrict__ X,
                                                const float* __restrict__ W,
                                                __half* __restrict__ Y,
                                                const int* __restrict__ src,
                                                const int* __restrict__ dst) {
    if (blockIdx.x >= GB1) {
        int e = (blockIdx.x - GB1) * 256 + threadIdx.x;
        if (e < N_EDGES) {
            atomicAdd(&g_atomic[A_DEGO + clampi(src[e])], 1);
            atomicAdd(&g_atomic[A_DEGI + clampi(dst[e])], 1);
        }
        return;
    }

    constexpr int LDA = 136, LDB = 136;
    extern __shared__ __half sm[];
    __half* sA = sm;
    __half* sB = sm + 128 * LDA;

    int t = threadIdx.x;
    int row0 = blockIdx.x * 128;

    {
        int kq = t & 15;
        int rr = t >> 4;
        const float4* X4 = (const float4*)X;
        const float4* W4 = (const float4*)W;
#pragma unroll
        for (int p = 0; p < 8; p++) {
            int r  = rr + p * 16;
            int gr = min(row0 + r, N_NODES - 1);
            float4 v0 = X4[(size_t)gr * 32 + kq * 2];
            float4 v1 = X4[(size_t)gr * 32 + kq * 2 + 1];
            *(uint4*)(sA + r * LDA + kq * 8) = f8_to_h8(v0, v1);
        }
#pragma unroll
        for (int p = 0; p < 8; p++) {
            int r = rr + p * 16;
            float4 v0 = W4[r * 32 + kq * 2];
            float4 v1 = W4[r * 32 + kq * 2 + 1];
            *(uint4*)(sB + r * LDB + kq * 8) = f8_to_h8(v0, v1);
        }
    }
    __syncthreads();

    int lane = t & 31;
    int wid  = t >> 5;
    int wm = wid >> 1;
    int wn = wid & 1;

    float acc[2][8][4];
#pragma unroll
    for (int i = 0; i < 2; i++)
#pragma unroll
        for (int j = 0; j < 8; j++)
#pragma unroll
            for (int q = 0; q < 4; q++) acc[i][j][q] = 0.f;

    uint32_t aaddr = s2u(sA) + (((wm * 32 + (lane & 15)) * LDA + (lane >> 4) * 8)) * 2;
    uint32_t baddr = s2u(sB) + ((((lane & 7) + ((lane >> 3) & 1) * 8) * LDB
                                 + wn * 64 + (lane >> 4) * 8)) * 2;

#pragma unroll
    for (int ks = 0; ks < 8; ks++) {
        uint32_t a[2][4];
        ldsm_x4(a[0][0], a[0][1], a[0][2], a[0][3], aaddr + ks * 32);
        ldsm_x4(a[1][0], a[1][1], a[1][2], a[1][3], aaddr + 16 * LDA * 2 + ks * 32);
        uint32_t b[8][2];
#pragma unroll
        for (int ntp = 0; ntp < 4; ntp++) {
            uint32_t r0, r1, r2, r3;
            ldsm_x4t(r0, r1, r2, r3, baddr + ks * 16 * LDB * 2 + ntp * 32);
            b[2 * ntp][0] = r0; b[2 * ntp][1] = r1;
            b[2 * ntp + 1][0] = r2; b[2 * ntp + 1][1] = r3;
        }
#pragma unroll
        for (int mt = 0; mt < 2; mt++)
#pragma unroll
            for (int nt = 0; nt < 8; nt++)
                mma16816(acc[mt][nt], a[mt], b[nt]);
    }

#pragma unroll
    for (int mt = 0; mt < 2; mt++) {
        int r1 = row0 + wm * 32 + mt * 16 + (lane >> 2);
#pragma unroll
        for (int nt = 0; nt < 8; nt++) {
            int c = wn * 64 + nt * 8 + ((lane & 3) << 1);
            __half2 lo = __floats2half2_rn(acc[mt][nt][0], acc[mt][nt][1]);
            __half2 hi = __floats2half2_rn(acc[mt][nt][2], acc[mt][nt][3]);
            if (r1 < N_NODES)     *(__half2*)(Y + (size_t)r1 * 128 + c)       = lo;
            if (r1 + 8 < N_NODES) *(__half2*)(Y + (size_t)(r1 + 8) * 128 + c) = hi;
        }
    }
}

// ---------------- single-pass scan (decoupled chaining) + norms + cursor init ----------------
__global__ __launch_bounds__(SCAN_B) void k_scan() {
    __shared__ int wt[32];
    __shared__ int s_prefix;
    int b    = blockIdx.x;
    int i    = b * SCAN_B + threadIdx.x;
    int lane = threadIdx.x & 31;
    int wid  = threadIdx.x >> 5;
    int v = (i < N_NODES) ? g_atomic[A_DEGI + i] : 0;
    if (i < N_NODES) {
        g_norm_in [i] = rsqrtf((float)max(v, 1));
        g_norm_out[i] = rsqrtf((float)max(g_atomic[A_DEGO + i], 1));
    }
    int x = v;
#pragma unroll
    for (int off = 1; off < 32; off <<= 1) {
        int t = __shfl_up_sync(0xffffffffu, x, off);
        if (lane >= off) x += t;
    }
    if (lane == 31) wt[wid] = x;
    __syncthreads();
    if (wid == 0) {
        int y = wt[lane];
#pragma unroll
        for (int off = 1; off < 32; off <<= 1) {
            int t = __shfl_up_sync(0xffffffffu, y, off);
            if (lane >= off) y += t;
        }
        wt[lane] = y;
    }
    __syncthreads();
    if (wid > 0) x += wt[wid - 1];
    // x = inclusive prefix within block; thread SCAN_B-1 holds the block total
    if (threadIdx.x == SCAN_B - 1) {
        int prefix = 0;
        if (b > 0) {
            while (atomicAdd(&g_atomic[A_FLAG + (b - 1)], 0) == 0) { }
            prefix = g_atomic[A_PREF + (b - 1)];
        }
        g_atomic[A_PREF + b] = prefix + x;
        __threadfence();
        atomicExch(&g_atomic[A_FLAG + b], 1);
        s_prefix = prefix;
    }
    __syncthreads();
    if (i < N_NODES) {
        int rs = x - v + s_prefix;
        g_row_start[i] = rs;
        g_cursor[i]    = rs;
    }
}

// ---------------- fill: 4 edges per thread for MLP ----------------
__global__ __launch_bounds__(256) void k_fill(const int* __restrict__ src, const int* __restrict__ dst) {
    int base = blockIdx.x * 1024 + threadIdx.x;
    int s[4], d[4];
    bool ok[4];
#pragma unroll
    for (int k = 0; k < 4; k++) {
        int e = base + k * 256;
        ok[k] = e < N_EDGES;
        s[k] = ok[k] ? src[e] : 0;
        d[k] = ok[k] ? dst[e] : 0;
    }
    int pos[4];
#pragma unroll
    for (int k = 0; k < 4; k++)
        if (ok[k]) pos[k] = atomicAdd(&g_cursor[clampi(d[k])], 1);
#pragma unroll
    for (int k = 0; k < 4; k++)
        if (ok[k]) g_csr_src[pos[k]] = clampi(s[k]);
}

// ======= fused B: gather1 (into smem A-tile, with epilogue) + tensor-core GEMM2 -> z2 =======
// block = 128 nodes, 256 threads (8 warps x 16 nodes each)
__global__ __launch_bounds__(256) void k_fusedB(const float* __restrict__ W,
                                                const float* __restrict__ b1,
                                                __half* __restrict__ Y) {
    constexpr int LDA = 136, LDB = 72;
    extern __shared__ __half sm[];
    __half* sA = sm;                 // gathered h1 tile [128][136]
    __half* sB = sm + 128 * LDA;     // W2 [128][72]

    int t = threadIdx.x;
    int lane = t & 31;
    int wid  = t >> 5;
    int row0 = blockIdx.x * 128;

    // load W2 into sB
    {
        int cq = t & 7;
        int r2 = t >> 3;
        const float4* W4 = (const float4*)W;
#pragma unroll
        for (int p = 0; p < 4; p++) {
            int r = r2 + p * 32;
            float4 v0 = W4[r * 16 + cq * 2];
            float4 v1 = W4[r * 16 + cq * 2 + 1];
            *(uint4*)(sB + r * LDB + cq * 8) = f8_to_h8(v0, v1);
        }
    }

    // gather phase: warp w handles local rows [w*16, w*16+16); lane owns 4 features (uint2)
    {
        const uint2* Z2 = (const uint2*)g_z1h;
        float4 b = ((const float4*)b1)[lane];
#pragma unroll 1
        for (int j = 0; j < 16; j++) {
            int r  = wid * 16 + j;
            int gr = row0 + r;
            uint2 u;
            if (gr < N_NODES) {
                int start = g_row_start[gr];
                int end   = start + g_atomic[A_DEGI + gr];
                float4 acc = make_float4(0.f, 0.f, 0.f, 0.f);
#pragma unroll 4
                for (int p = start; p < end; p++) {
                    int s = __ldg(&g_csr_src[p]);
                    float ns = __ldg(&g_norm_out[s]);      // warp-uniform broadcast
                    uint2 v = __ldg(&Z2[(size_t)s * 32 + lane]);
                    float2 f0 = __half22float2(*(__half2*)&v.x);
                    float2 f1 = __half22float2(*(__half2*)&v.y);
                    acc.x = fmaf(f0.x, ns, acc.x);
                    acc.y = fmaf(f0.y, ns, acc.y);
                    acc.z = fmaf(f1.x, ns, acc.z);
                    acc.w = fmaf(f1.y, ns, acc.w);
                }
                float ni = g_norm_in[gr];
                float no = g_norm_out[gr];
                float4 o;
                o.x = fmaxf(fmaf(acc.x, ni, b.x), 0.f) * no;
                o.y = fmaxf(fmaf(acc.y, ni, b.y), 0.f) * no;
                o.z = fmaxf(fmaf(acc.z, ni, b.z), 0.f) * no;
                o.w = fmaxf(fmaf(acc.w, ni, b.w), 0.f) * no;
                __half2 h0 = __floats2half2_rn(o.x, o.y);
                __half2 h1v = __floats2half2_rn(o.z, o.w);
                u.x = *(uint32_t*)&h0; u.y = *(uint32_t*)&h1v;
            } else {
                u.x = 0u; u.y = 0u;
            }
            *(uint2*)(sA + r * LDA + lane * 4) = u;
        }
    }
    __syncthreads();

    // GEMM2 phase: 8 warps (4 M x 2 N), warp tile 32x32
    int wm = wid >> 1;
    int wn = wid & 1;

    float acc[2][4][4];
#pragma unroll
    for (int i = 0; i < 2; i++)
#pragma unroll
        for (int j = 0; j < 4; j++)
#pragma unroll
            for (int q = 0; q < 4; q++) acc[i][j][q] = 0.f;

    uint32_t aaddr = s2u(sA) + (((wm * 32 + (lane & 15)) * LDA + (lane >> 4) * 8)) * 2;
    uint32_t baddr = s2u(sB) + ((((lane & 7) + ((lane >> 3) & 1) * 8) * LDB
                                 + wn * 32 + (lane >> 4) * 8)) * 2;

#pragma unroll
    for (int ks = 0; ks < 8; ks++) {
        uint32_t a[2][4];
        ldsm_x4(a[0][0], a[0][1], a[0][2], a[0][3], aaddr + ks * 32);
        ldsm_x4(a[1][0], a[1][1], a[1][2], a[1][3], aaddr + 16 * LDA * 2 + ks * 32);
        uint32_t b[4][2];
#pragma unroll
        for (int ntp = 0; ntp < 2; ntp++) {
            uint32_t r0, r1, r2, r3;
            ldsm_x4t(r0, r1, r2, r3, baddr + ks * 16 * LDB * 2 + ntp * 32);
            b[2 * ntp][0] = r0; b[2 * ntp][1] = r1;
            b[2 * ntp + 1][0] = r2; b[2 * ntp + 1][1] = r3;
        }
#pragma unroll
        for (int mt = 0; mt < 2; mt++)
#pragma unroll
            for (int nt = 0; nt < 4; nt++)
                mma16816(acc[mt][nt], a[mt], b[nt]);
    }

#pragma unroll
    for (int mt = 0; mt < 2; mt++) {
        int r1 = row0 + wm * 32 + mt * 16 + (lane >> 2);
#pragma unroll
        for (int nt = 0; nt < 4; nt++) {
            int c = wn * 32 + nt * 8 + ((lane & 3) << 1);
            __half2 lo = __floats2half2_rn(acc[mt][nt][0], acc[mt][nt][1]);
            __half2 hi = __floats2half2_rn(acc[mt][nt][2], acc[mt][nt][3]);
            if (r1 < N_NODES)     *(__half2*)(Y + (size_t)r1 * 64 + c)       = lo;
            if (r1 + 8 < N_NODES) *(__half2*)(Y + (size_t)(r1 + 8) * 64 + c) = hi;
        }
    }
}

// ---------------- gather2: out = relu( (sum z2[src]) * norm_in + b2 ) ----------------
__global__ void k_gather2(const float* __restrict__ b2, float* __restrict__ out) {
    int warp = (blockIdx.x * blockDim.x + threadIdx.x) >> 5;
    int lane = threadIdx.x & 31;
    if (warp >= N_NODES) return;
    int start = g_row_start[warp];
    int end   = start + g_atomic[A_DEGI + warp];
    const uint32_t* Y1 = (const uint32_t*)g_z2h;
    float2 acc = make_float2(0.f, 0.f);
#pragma unroll 4
    for (int p = start; p < end; p++) {
        int s = __ldg(&g_csr_src[p]);
        uint32_t v = __ldg(&Y1[(size_t)s * 32 + lane]);
        float2 f = __half22float2(*(__half2*)&v);
        acc.x += f.x; acc.y += f.y;
    }
    float ni = g_norm_in[warp];
    float2 b = ((const float2*)b2)[lane];
    float2 o;
    o.x = fmaxf(fmaf(acc.x, ni, b.x), 0.f);
    o.y = fmaxf(fmaf(acc.y, ni, b.y), 0.f);
    ((float2*)out)[(size_t)warp * 32 + lane] = o;
}

// ---------------- launch ----------------
extern "C" void kernel_launch(void* const* d_in, const int* in_sizes, int n_in,
                              void* d_out, int out_size) {
    const float* h   = (const float*)d_in[0];
    const float* W1  = (const float*)d_in[1];
    const float* b1  = (const float*)d_in[2];
    const float* W2  = (const float*)d_in[3];
    const float* b2  = (const float*)d_in[4];
    const int*   src = (const int*)d_in[5];   // JAX x64-disabled: int32
    const int*   dst = (const int*)d_in[6];
    float*       out = (float*)d_out;

    __half *z1h, *z2h;
    int* atom;
    cudaGetSymbolAddress((void**)&z1h,  g_z1h);
    cudaGetSymbolAddress((void**)&z2h,  g_z2h);
    cudaGetSymbolAddress((void**)&atom, g_atomic);

    const int SMEM1 = (128 * 136 + 128 * 136) * 2;   // 69632 B
    const int SMEM2 = (128 * 136 + 128 * 72) * 2;    // 53248 B
    cudaFuncSetAttribute((const void*)k_fusedA,
                         cudaFuncAttributeMaxDynamicSharedMemorySize, SMEM1);
    cudaFuncSetAttribute((const void*)k_fusedB,
                         cudaFuncAttributeMaxDynamicSharedMemorySize, SMEM2);

    const int T = 256;

    cudaMemsetAsync(atom, 0, A_TOTAL * sizeof(int));
    k_fusedA<<<GB1 + DEGB, T, SMEM1>>>(h, W1, z1h, src, dst);   // gemm1 || deg
    k_scan  <<<SCAN_NB, SCAN_B>>>();                            // norms + row_start + cursor
    k_fill  <<<(N_EDGES + 1023) / 1024, T>>>(src, dst);         // CSR fill (4 edges/thread)
    k_fusedB<<<GB1, T, SMEM2>>>(W2, b1, z2h);                   // gather1 + gemm2
    k_gather2<<<(N_NODES * 32 + T - 1) / T, T>>>(b2, out);
}

// round 10
// speedup vs baseline: 1.1115x; 1.1115x over previous
#include <cuda_runtime.h>
#include <cuda_fp16.h>
#include <cstdint>

#define N_NODES 50000
#define N_EDGES 800000
#define F_IN    128
#define F_HID   128
#define F_OUT   64
#define SCAN_B  1024
#define SCAN_NB ((N_NODES + SCAN_B - 1) / SCAN_B)   // 49
#define GB1     ((N_NODES + 127) / 128)             // 391 gemm1 blocks
#define DEGB    ((N_EDGES + 255) / 256)             // 3125 deg blocks

// ---- zero-init region (single memset): [0,N)=deg_out [N,2N)=deg_in [2N,2N+64)=scan flags ----
#define A_DEGO  0
#define A_DEGI  N_NODES
#define A_FLAG  (2 * N_NODES)
#define A_PREF  (2 * N_NODES + 64)
#define A_TOTAL (2 * N_NODES + 128)
__device__ __align__(16) int    g_atomic[A_TOTAL];

__device__ __align__(16) __half g_z1h[N_NODES * F_HID];  // h@W1                  fp16 [N,128]
__device__ __align__(16) __half g_h1h[N_NODES * F_HID];  // relu layer1 *norm_out fp16 [N,128]
__device__ __align__(16) __half g_z2h[N_NODES * F_OUT];  // h1@W2                 fp16 [N,64]
__device__ __align__(16) float  g_norm_out[N_NODES];
__device__ __align__(16) float  g_norm_in [N_NODES];
__device__ __align__(16) int    g_row_start[N_NODES];
__device__ __align__(16) int    g_cursor[N_NODES];
__device__ __align__(16) int    g_csr_src[N_EDGES];

__device__ __forceinline__ int clampi(int v) {
    return v < 0 ? 0 : (v >= N_NODES ? N_NODES - 1 : v);
}

__device__ __forceinline__ uint32_t s2u(const void* p) {
    uint32_t a;
    asm("{ .reg .u64 t; cvta.to.shared.u64 t, %1; cvt.u32.u64 %0, t; }" : "=r"(a) : "l"(p));
    return a;
}

__device__ __forceinline__ void ldsm_x4(uint32_t& r0, uint32_t& r1, uint32_t& r2, uint32_t& r3, uint32_t addr) {
    asm volatile("ldmatrix.sync.aligned.m8n8.x4.shared.b16 {%0,%1,%2,%3}, [%4];"
                 : "=r"(r0), "=r"(r1), "=r"(r2), "=r"(r3) : "r"(addr));
}

__device__ __forceinline__ void ldsm_x4t(uint32_t& r0, uint32_t& r1, uint32_t& r2, uint32_t& r3, uint32_t addr) {
    asm volatile("ldmatrix.sync.aligned.m8n8.x4.trans.shared.b16 {%0,%1,%2,%3}, [%4];"
                 : "=r"(r0), "=r"(r1), "=r"(r2), "=r"(r3) : "r"(addr));
}

__device__ __forceinline__ void mma16816(float* c, const uint32_t* a, const uint32_t* b) {
    asm volatile("mma.sync.aligned.m16n8k16.row.col.f32.f16.f16.f32 "
                 "{%0,%1,%2,%3}, {%4,%5,%6,%7}, {%8,%9}, {%0,%1,%2,%3};"
                 : "+f"(c[0]), "+f"(c[1]), "+f"(c[2]), "+f"(c[3])
                 : "r"(a[0]), "r"(a[1]), "r"(a[2]), "r"(a[3]), "r"(b[0]), "r"(b[1]));
}

__device__ __forceinline__ uint4 f8_to_h8(float4 v0, float4 v1) {
    __half2 h0 = __floats2half2_rn(v0.x, v0.y);
    __half2 h1 = __floats2half2_rn(v0.z, v0.w);
    __half2 h2 = __floats2half2_rn(v1.x, v1.y);
    __half2 h3 = __floats2half2_rn(v1.z, v1.w);
    uint4 u;
    u.x = *(uint32_t*)&h0; u.y = *(uint32_t*)&h1;
    u.z = *(uint32_t*)&h2; u.w = *(uint32_t*)&h3;
    return u;
}

// ======= fused A: blocks [0,GB1) = GEMM1 (z1 = fp16(h@W1)); blocks [GB1,..) = degree histogram =======
__global__ __launch_bounds__(256) void k_fusedA(const float* __restrict__ X,
                                                const float* __restrict__ W,
                                                __half* __restrict__ Y,
                                                const int* __restrict__ src,
                                                const int* __restrict__ dst) {
    if (blockIdx.x >= GB1) {
        int e = (blockIdx.x - GB1) * 256 + threadIdx.x;
        if (e < N_EDGES) {
            atomicAdd(&g_atomic[A_DEGO + clampi(src[e])], 1);
            atomicAdd(&g_atomic[A_DEGI + clampi(dst[e])], 1);
        }
        return;
    }

    constexpr int LDA = 136, LDB = 136;
    extern __shared__ __half sm[];
    __half* sA = sm;
    __half* sB = sm + 128 * LDA;

    int t = threadIdx.x;
    int row0 = blockIdx.x * 128;

    {
        int kq = t & 15;
        int rr = t >> 4;
        const float4* X4 = (const float4*)X;
        const float4* W4 = (const float4*)W;
#pragma unroll
        for (int p = 0; p < 8; p++) {
            int r  = rr + p * 16;
            int gr = min(row0 + r, N_NODES - 1);
            float4 v0 = X4[(size_t)gr * 32 + kq * 2];
            float4 v1 = X4[(size_t)gr * 32 + kq * 2 + 1];
            *(uint4*)(sA + r * LDA + kq * 8) = f8_to_h8(v0, v1);
        }
#pragma unroll
        for (int p = 0; p < 8; p++) {
            int r = rr + p * 16;
            float4 v0 = W4[r * 32 + kq * 2];
            float4 v1 = W4[r * 32 + kq * 2 + 1];
            *(uint4*)(sB + r * LDB + kq * 8) = f8_to_h8(v0, v1);
        }
    }
    __syncthreads();

    int lane = t & 31;
    int wid  = t >> 5;
    int wm = wid >> 1;
    int wn = wid & 1;

    float acc[2][8][4];
#pragma unroll
    for (int i = 0; i < 2; i++)
#pragma unroll
        for (int j = 0; j < 8; j++)
#pragma unroll
            for (int q = 0; q < 4; q++) acc[i][j][q] = 0.f;

    uint32_t aaddr = s2u(sA) + (((wm * 32 + (lane & 15)) * LDA + (lane >> 4) * 8)) * 2;
    uint32_t baddr = s2u(sB) + ((((lane & 7) + ((lane >> 3) & 1) * 8) * LDB
                                 + wn * 64 + (lane >> 4) * 8)) * 2;

#pragma unroll
    for (int ks = 0; ks < 8; ks++) {
        uint32_t a[2][4];
        ldsm_x4(a[0][0], a[0][1], a[0][2], a[0][3], aaddr + ks * 32);
        ldsm_x4(a[1][0], a[1][1], a[1][2], a[1][3], aaddr + 16 * LDA * 2 + ks * 32);
        uint32_t b[8][2];
#pragma unroll
        for (int ntp = 0; ntp < 4; ntp++) {
            uint32_t r0, r1, r2, r3;
            ldsm_x4t(r0, r1, r2, r3, baddr + ks * 16 * LDB * 2 + ntp * 32);
            b[2 * ntp][0] = r0; b[2 * ntp][1] = r1;
            b[2 * ntp + 1][0] = r2; b[2 * ntp + 1][1] = r3;
        }
#pragma unroll
        for (int mt = 0; mt < 2; mt++)
#pragma unroll
            for (int nt = 0; nt < 8; nt++)
                mma16816(acc[mt][nt], a[mt], b[nt]);
    }

#pragma unroll
    for (int mt = 0; mt < 2; mt++) {
        int r1 = row0 + wm * 32 + mt * 16 + (lane >> 2);
#pragma unroll
        for (int nt = 0; nt < 8; nt++) {
            int c = wn * 64 + nt * 8 + ((lane & 3) << 1);
            __half2 lo = __floats2half2_rn(acc[mt][nt][0], acc[mt][nt][1]);
            __half2 hi = __floats2half2_rn(acc[mt][nt][2], acc[mt][nt][3]);
            if (r1 < N_NODES)     *(__half2*)(Y + (size_t)r1 * 128 + c)       = lo;
            if (r1 + 8 < N_NODES) *(__half2*)(Y + (size_t)(r1 + 8) * 128 + c) = hi;
        }
    }
}

// ---------------- single-pass scan (decoupled chaining) + norms + cursor init ----------------
__global__ __launch_bounds__(SCAN_B) void k_scan() {
    __shared__ int wt[32];
    __shared__ int s_prefix;
    int b    = blockIdx.x;
    int i    = b * SCAN_B + threadIdx.x;
    int lane = threadIdx.x & 31;
    int wid  = threadIdx.x >> 5;
    int v = (i < N_NODES) ? g_atomic[A_DEGI + i] : 0;
    if (i < N_NODES) {
        g_norm_in [i] = rsqrtf((float)max(v, 1));
        g_norm_out[i] = rsqrtf((float)max(g_atomic[A_DEGO + i], 1));
    }
    int x = v;
#pragma unroll
    for (int off = 1; off < 32; off <<= 1) {
        int t = __shfl_up_sync(0xffffffffu, x, off);
        if (lane >= off) x += t;
    }
    if (lane == 31) wt[wid] = x;
    __syncthreads();
    if (wid == 0) {
        int y = wt[lane];
#pragma unroll
        for (int off = 1; off < 32; off <<= 1) {
            int t = __shfl_up_sync(0xffffffffu, y, off);
            if (lane >= off) y += t;
        }
        wt[lane] = y;
    }
    __syncthreads();
    if (wid > 0) x += wt[wid - 1];
    if (threadIdx.x == SCAN_B - 1) {
        int prefix = 0;
        if (b > 0) {
            while (atomicAdd(&g_atomic[A_FLAG + (b - 1)], 0) == 0) { }
            prefix = g_atomic[A_PREF + (b - 1)];
        }
        g_atomic[A_PREF + b] = prefix + x;
        __threadfence();
        atomicExch(&g_atomic[A_FLAG + b], 1);
        s_prefix = prefix;
    }
    __syncthreads();
    if (i < N_NODES) {
        int rs = x - v + s_prefix;
        g_row_start[i] = rs;
        g_cursor[i]    = rs;
    }
}

// ---------------- fill: 4 edges per thread for MLP ----------------
__global__ __launch_bounds__(256) void k_fill(const int* __restrict__ src, const int* __restrict__ dst) {
    int base = blockIdx.x * 1024 + threadIdx.x;
    int s[4], d[4];
    bool ok[4];
#pragma unroll
    for (int k = 0; k < 4; k++) {
        int e = base + k * 256;
        ok[k] = e < N_EDGES;
        s[k] = ok[k] ? src[e] : 0;
        d[k] = ok[k] ? dst[e] : 0;
    }
    int pos[4];
#pragma unroll
    for (int k = 0; k < 4; k++)
        if (ok[k]) pos[k] = atomicAdd(&g_cursor[clampi(d[k])], 1);
#pragma unroll
    for (int k = 0; k < 4; k++)
        if (ok[k]) g_csr_src[pos[k]] = clampi(s[k]);
}

// ---------------- gather1: h1 = fp16( relu( (sum no[s]*z1[s]) * ni + b1 ) * no ) ----------------
// one warp per node; lane owns 4 features (uint2 = 2 half2)
__global__ void k_gather1(const float* __restrict__ b1) {
    int warp = (blockIdx.x * blockDim.x + threadIdx.x) >> 5;
    int lane = threadIdx.x & 31;
    if (warp >= N_NODES) return;
    int start = g_row_start[warp];
    int end   = start + g_atomic[A_DEGI + warp];
    const uint2* Z2 = (const uint2*)g_z1h;
    float4 acc = make_float4(0.f, 0.f, 0.f, 0.f);
#pragma unroll 4
    for (int p = start; p < end; p++) {
        int s = __ldg(&g_csr_src[p]);
        float ns = __ldg(&g_norm_out[s]);          // warp-uniform broadcast
        uint2 v = __ldg(&Z2[(size_t)s * 32 + lane]);
        float2 f0 = __half22float2(*(__half2*)&v.x);
        float2 f1 = __half22float2(*(__half2*)&v.y);
        acc.x = fmaf(f0.x, ns, acc.x);
        acc.y = fmaf(f0.y, ns, acc.y);
        acc.z = fmaf(f1.x, ns, acc.z);
        acc.w = fmaf(f1.y, ns, acc.w);
    }
    float ni = g_norm_in[warp];
    float no = g_norm_out[warp];
    float4 b = ((const float4*)b1)[lane];
    float4 o;
    o.x = fmaxf(fmaf(acc.x, ni, b.x), 0.f) * no;
    o.y = fmaxf(fmaf(acc.y, ni, b.y), 0.f) * no;
    o.z = fmaxf(fmaf(acc.z, ni, b.z), 0.f) * no;
    o.w = fmaxf(fmaf(acc.w, ni, b.w), 0.f) * no;
    __half2 h0 = __floats2half2_rn(o.x, o.y);
    __half2 h1v = __floats2half2_rn(o.z, o.w);
    uint2 u;
    u.x = *(uint32_t*)&h0; u.y = *(uint32_t*)&h1v;
    ((uint2*)g_h1h)[(size_t)warp * 32 + lane] = u;
}

// ---------------- tensor-core GEMM2: z2 = fp16( h1 @ W2 ) ----------------
__global__ __launch_bounds__(256) void k_gemm2(const __half* __restrict__ Xh,
                                               const float* __restrict__ W,
                                               __half* __restrict__ Y) {
    constexpr int LDA = 136, LDB = 72;
    extern __shared__ __half sm[];
    __half* sA = sm;
    __half* sB = sm + 128 * LDA;

    int t = threadIdx.x;
    int row0 = blockIdx.x * 128;

    {
        int kq = t & 15;
        int rr = t >> 4;
        const uint4* X4 = (const uint4*)Xh;
#pragma unroll
        for (int p = 0; p < 8; p++) {
            int r  = rr + p * 16;
            int gr = min(row0 + r, N_NODES - 1);
            *(uint4*)(sA + r * LDA + kq * 8) = X4[(size_t)gr * 16 + kq];
        }
        int cq = t & 7;
        int r2 = t >> 3;
        const float4* W4 = (const float4*)W;
#pragma unroll
        for (int p = 0; p < 4; p++) {
            int r = r2 + p * 32;
            float4 v0 = W4[r * 16 + cq * 2];
            float4 v1 = W4[r * 16 + cq * 2 + 1];
            *(uint4*)(sB + r * LDB + cq * 8) = f8_to_h8(v0, v1);
        }
    }
    __syncthreads();

    int lane = t & 31;
    int wid  = t >> 5;
    int wm = wid >> 1;
    int wn = wid & 1;

    float acc[2][4][4];
#pragma unroll
    for (int i = 0; i < 2; i++)
#pragma unroll
        for (int j = 0; j < 4; j++)
#pragma unroll
            for (int q = 0; q < 4; q++) acc[i][j][q] = 0.f;

    uint32_t aaddr = s2u(sA) + (((wm * 32 + (lane & 15)) * LDA + (lane >> 4) * 8)) * 2;
    uint32_t baddr = s2u(sB) + ((((lane & 7) + ((lane >> 3) & 1) * 8) * LDB
                                 + wn * 32 + (lane >> 4) * 8)) * 2;

#pragma unroll
    for (int ks = 0; ks < 8; ks++) {
        uint32_t a[2][4];
        ldsm_x4(a[0][0], a[0][1], a[0][2], a[0][3], aaddr + ks * 32);
        ldsm_x4(a[1][0], a[1][1], a[1][2], a[1][3], aaddr + 16 * LDA * 2 + ks * 32);
        uint32_t b[4][2];
#pragma unroll
        for (int ntp = 0; ntp < 2; ntp++) {
            uint32_t r0, r1, r2, r3;
            ldsm_x4t(r0, r1, r2, r3, baddr + ks * 16 * LDB * 2 + ntp * 32);
            b[2 * ntp][0] = r0; b[2 * ntp][1] = r1;
            b[2 * ntp + 1][0] = r2; b[2 * ntp + 1][1] = r3;
        }
#pragma unroll
        for (int mt = 0; mt < 2; mt++)
#pragma unroll
            for (int nt = 0; nt < 4; nt++)
                mma16816(acc[mt][nt], a[mt], b[nt]);
    }

#pragma unroll
    for (int mt = 0; mt < 2; mt++) {
        int r1 = row0 + wm * 32 + mt * 16 + (lane >> 2);
#pragma unroll
        for (int nt = 0; nt < 4; nt++) {
            int c = wn * 32 + nt * 8 + ((lane & 3) << 1);
            __half2 lo = __floats2half2_rn(acc[mt][nt][0], acc[mt][nt][1]);
            __half2 hi = __floats2half2_rn(acc[mt][nt][2], acc[mt][nt][3]);
            if (r1 < N_NODES)     *(__half2*)(Y + (size_t)r1 * 64 + c)       = lo;
            if (r1 + 8 < N_NODES) *(__half2*)(Y + (size_t)(r1 + 8) * 64 + c) = hi;
        }
    }
}

// ---------------- gather2: out = relu( (sum z2[src]) * norm_in + b2 ) ----------------
__global__ void k_gather2(const float* __restrict__ b2, float* __restrict__ out) {
    int warp = (blockIdx.x * blockDim.x + threadIdx.x) >> 5;
    int lane = threadIdx.x & 31;
    if (warp >= N_NODES) return;
    int start = g_row_start[warp];
    int end   = start + g_atomic[A_DEGI + warp];
    const uint32_t* Y1 = (const uint32_t*)g_z2h;
    float2 acc = make_float2(0.f, 0.f);
#pragma unroll 4
    for (int p = start; p < end; p++) {
        int s = __ldg(&g_csr_src[p]);
        uint32_t v = __ldg(&Y1[(size_t)s * 32 + lane]);
        float2 f = __half22float2(*(__half2*)&v);
        acc.x += f.x; acc.y += f.y;
    }
    float ni = g_norm_in[warp];
    float2 b = ((const float2*)b2)[lane];
    float2 o;
    o.x = fmaxf(fmaf(acc.x, ni, b.x), 0.f);
    o.y = fmaxf(fmaf(acc.y, ni, b.y), 0.f);
    ((float2*)out)[(size_t)warp * 32 + lane] = o;
}

// ---------------- launch ----------------
extern "C" void kernel_launch(void* const* d_in, const int* in_sizes, int n_in,
                              void* d_out, int out_size) {
    const float* h   = (const float*)d_in[0];
    const float* W1  = (const float*)d_in[1];
    const float* b1  = (const float*)d_in[2];
    const float* W2  = (const float*)d_in[3];
    const float* b2  = (const float*)d_in[4];
    const int*   src = (const int*)d_in[5];   // JAX x64-disabled: int32
    const int*   dst = (const int*)d_in[6];
    float*       out = (float*)d_out;

    __half *z1h, *h1h, *z2h;
    int* atom;
    cudaGetSymbolAddress((void**)&z1h,  g_z1h);
    cudaGetSymbolAddress((void**)&h1h,  g_h1h);
    cudaGetSymbolAddress((void**)&z2h,  g_z2h);
    cudaGetSymbolAddress((void**)&atom, g_atomic);

    const int SMEM1 = (128 * 136 + 128 * 136) * 2;   // 69632 B
    const int SMEM2 = (128 * 136 + 128 * 72) * 2;    // 53248 B
    cudaFuncSetAttribute((const void*)k_fusedA,
                         cudaFuncAttributeMaxDynamicSharedMemorySize, SMEM1);
    cudaFuncSetAttribute((const void*)k_gemm2,
                         cudaFuncAttributeMaxDynamicSharedMemorySize, SMEM2);

    const int T = 256;

    cudaMemsetAsync(atom, 0, A_TOTAL * sizeof(int));
    k_fusedA<<<GB1 + DEGB, T, SMEM1>>>(h, W1, z1h, src, dst);    // 1: gemm1 || deg
    k_scan  <<<SCAN_NB, SCAN_B>>>();                             // 2: norms + row_start + cursor
    k_fill  <<<(N_EDGES + 1023) / 1024, T>>>(src, dst);          // 3: CSR fill (4 edges/thread)
    k_gather1<<<(N_NODES * 32 + T - 1) / T, T>>>(b1);            // 4 (profiled slot = idx 3 incl. memset)
    k_gemm2 <<<GB1, T, SMEM2>>>(h1h, W2, z2h);                   // 5
    k_gather2<<<(N_NODES * 32 + T - 1) / T, T>>>(b2, out);       // 6
}

// round 11
// speedup vs baseline: 1.5686x; 1.4112x over previous
#include <cuda_runtime.h>
#include <cuda_fp16.h>
#include <cstdint>

#define N_NODES 50000
#define N_EDGES 800000
#define F_IN    128
#define F_HID   128
#define F_OUT   64
#define SCAN_B  1024
#define SCAN_NB ((N_NODES + SCAN_B - 1) / SCAN_B)   // 49
#define GB1     ((N_NODES + 127) / 128)             // 391 gemm1 blocks
#define DEGB    ((N_EDGES + 255) / 256)             // 3125 deg blocks

// ---- zero-init region (single memset): [0,N)=deg_out [N,2N)=deg_in ----
#define A_DEGO  0
#define A_DEGI  N_NODES
#define A_TOTAL (2 * N_NODES)
__device__ __align__(16) int    g_atomic[A_TOTAL];

__device__ __align__(16) float  g_z1f[N_NODES * F_HID];  // h@W1                  fp32 [N,128]
__device__ __align__(16) __half g_h1h[N_NODES * F_HID];  // relu layer1 *norm_out fp16 [N,128]
__device__ __align__(16) float  g_z2f[N_NODES * F_OUT];  // h1@W2                 fp32 [N,64]
__device__ __align__(16) float  g_norm_out[N_NODES];
__device__ __align__(16) float  g_norm_in [N_NODES];
__device__ __align__(16) int    g_row_start[N_NODES];
__device__ __align__(16) int    g_cursor[N_NODES];
__device__ __align__(16) int    g_bsum[64];
__device__ __align__(16) int    g_csr_src[N_EDGES];

__device__ __forceinline__ int clampi(int v) {
    return v < 0 ? 0 : (v >= N_NODES ? N_NODES - 1 : v);
}

__device__ __forceinline__ uint32_t s2u(const void* p) {
    uint32_t a;
    asm("{ .reg .u64 t; cvta.to.shared.u64 t, %1; cvt.u32.u64 %0, t; }" : "=r"(a) : "l"(p));
    return a;
}

__device__ __forceinline__ void ldsm_x4(uint32_t& r0, uint32_t& r1, uint32_t& r2, uint32_t& r3, uint32_t addr) {
    asm volatile("ldmatrix.sync.aligned.m8n8.x4.shared.b16 {%0,%1,%2,%3}, [%4];"
                 : "=r"(r0), "=r"(r1), "=r"(r2), "=r"(r3) : "r"(addr));
}

__device__ __forceinline__ void ldsm_x4t(uint32_t& r0, uint32_t& r1, uint32_t& r2, uint32_t& r3, uint32_t addr) {
    asm volatile("ldmatrix.sync.aligned.m8n8.x4.trans.shared.b16 {%0,%1,%2,%3}, [%4];"
                 : "=r"(r0), "=r"(r1), "=r"(r2), "=r"(r3) : "r"(addr));
}

__device__ __forceinline__ void mma16816(float* c, const uint32_t* a, const uint32_t* b) {
    asm volatile("mma.sync.aligned.m16n8k16.row.col.f32.f16.f16.f32 "
                 "{%0,%1,%2,%3}, {%4,%5,%6,%7}, {%8,%9}, {%0,%1,%2,%3};"
                 : "+f"(c[0]), "+f"(c[1]), "+f"(c[2]), "+f"(c[3])
                 : "r"(a[0]), "r"(a[1]), "r"(a[2]), "r"(a[3]), "r"(b[0]), "r"(b[1]));
}

__device__ __forceinline__ uint4 f8_to_h8(float4 v0, float4 v1) {
    __half2 h0 = __floats2half2_rn(v0.x, v0.y);
    __half2 h1 = __floats2half2_rn(v0.z, v0.w);
    __half2 h2 = __floats2half2_rn(v1.x, v1.y);
    __half2 h3 = __floats2half2_rn(v1.z, v1.w);
    uint4 u;
    u.x = *(uint32_t*)&h0; u.y = *(uint32_t*)&h1;
    u.z = *(uint32_t*)&h2; u.w = *(uint32_t*)&h3;
    return u;
}

// ======= fused A: blocks [0,GB1) = GEMM1 (z1 = fp32(h@W1)); blocks [GB1,..) = degree histogram =======
__global__ __launch_bounds__(256) void k_fusedA(const float* __restrict__ X,
                                                const float* __restrict__ W,
                                                float* __restrict__ Y,
                                                const int* __restrict__ src,
                                                const int* __restrict__ dst) {
    if (blockIdx.x >= GB1) {
        int e = (blockIdx.x - GB1) * 256 + threadIdx.x;
        if (e < N_EDGES) {
            atomicAdd(&g_atomic[A_DEGO + clampi(src[e])], 1);
            atomicAdd(&g_atomic[A_DEGI + clampi(dst[e])], 1);
        }
        return;
    }

    constexpr int LDA = 136, LDB = 136;
    extern __shared__ __half sm[];
    __half* sA = sm;
    __half* sB = sm + 128 * LDA;

    int t = threadIdx.x;
    int row0 = blockIdx.x * 128;

    {
        int kq = t & 15;
        int rr = t >> 4;
        const float4* X4 = (const float4*)X;
        const float4* W4 = (const float4*)W;
#pragma unroll
        for (int p = 0; p < 8; p++) {
            int r  = rr + p * 16;
            int gr = min(row0 + r, N_NODES - 1);
            float4 v0 = X4[(size_t)gr * 32 + kq * 2];
            float4 v1 = X4[(size_t)gr * 32 + kq * 2 + 1];
            *(uint4*)(sA + r * LDA + kq * 8) = f8_to_h8(v0, v1);
        }
#pragma unroll
        for (int p = 0; p < 8; p++) {
            int r = rr + p * 16;
            float4 v0 = W4[r * 32 + kq * 2];
            float4 v1 = W4[r * 32 + kq * 2 + 1];
            *(uint4*)(sB + r * LDB + kq * 8) = f8_to_h8(v0, v1);
        }
    }
    __syncthreads();

    int lane = t & 31;
    int wid  = t >> 5;
    int wm = wid >> 1;
    int wn = wid & 1;

    float acc[2][8][4];
#pragma unroll
    for (int i = 0; i < 2; i++)
#pragma unroll
        for (int j = 0; j < 8; j++)
#pragma unroll
            for (int q = 0; q < 4; q++) acc[i][j][q] = 0.f;

    uint32_t aaddr = s2u(sA) + (((wm * 32 + (lane & 15)) * LDA + (lane >> 4) * 8)) * 2;
    uint32_t baddr = s2u(sB) + ((((lane & 7) + ((lane >> 3) & 1) * 8) * LDB
                                 + wn * 64 + (lane >> 4) * 8)) * 2;

#pragma unroll
    for (int ks = 0; ks < 8; ks++) {
        uint32_t a[2][4];
        ldsm_x4(a[0][0], a[0][1], a[0][2], a[0][3], aaddr + ks * 32);
        ldsm_x4(a[1][0], a[1][1], a[1][2], a[1][3], aaddr + 16 * LDA * 2 + ks * 32);
        uint32_t b[8][2];
#pragma unroll
        for (int ntp = 0; ntp < 4; ntp++) {
            uint32_t r0, r1, r2, r3;
            ldsm_x4t(r0, r1, r2, r3, baddr + ks * 16 * LDB * 2 + ntp * 32);
            b[2 * ntp][0] = r0; b[2 * ntp][1] = r1;
            b[2 * ntp + 1][0] = r2; b[2 * ntp + 1][1] = r3;
        }
#pragma unroll
        for (int mt = 0; mt < 2; mt++)
#pragma unroll
            for (int nt = 0; nt < 8; nt++)
                mma16816(acc[mt][nt], a[mt], b[nt]);
    }

#pragma unroll
    for (int mt = 0; mt < 2; mt++) {
        int r1 = row0 + wm * 32 + mt * 16 + (lane >> 2);
#pragma unroll
        for (int nt = 0; nt < 8; nt++) {
            int c = wn * 64 + nt * 8 + ((lane & 3) << 1);
            if (r1 < N_NODES)
                *(float2*)(Y + (size_t)r1 * 128 + c)       = make_float2(acc[mt][nt][0], acc[mt][nt][1]);
            if (r1 + 8 < N_NODES)
                *(float2*)(Y + (size_t)(r1 + 8) * 128 + c) = make_float2(acc[mt][nt][2], acc[mt][nt][3]);
        }
    }
}

// ---------------- scan1: block-local scan of deg_in + fused norms ----------------
__global__ void k_scan1() {
    __shared__ int wt[32];
    int i    = blockIdx.x * SCAN_B + threadIdx.x;
    int lane = threadIdx.x & 31;
    int wid  = threadIdx.x >> 5;
    int v = (i < N_NODES) ? g_atomic[A_DEGI + i] : 0;
    if (i < N_NODES) {
        g_norm_in [i] = rsqrtf((float)max(v, 1));
        g_norm_out[i] = rsqrtf((float)max(g_atomic[A_DEGO + i], 1));
    }
    int x = v;
#pragma unroll
    for (int off = 1; off < 32; off <<= 1) {
        int t = __shfl_up_sync(0xffffffffu, x, off);
        if (lane >= off) x += t;
    }
    if (lane == 31) wt[wid] = x;
    __syncthreads();
    if (wid == 0) {
        int y = wt[lane];
#pragma unroll
        for (int off = 1; off < 32; off <<= 1) {
            int t = __shfl_up_sync(0xffffffffu, y, off);
            if (lane >= off) y += t;
        }
        wt[lane] = y;
    }
    __syncthreads();
    if (wid > 0) x += wt[wid - 1];
    if (i < N_NODES) g_row_start[i] = x - v;
    if (threadIdx.x == SCAN_B - 1) g_bsum[blockIdx.x] = x;
}

// ---------------- scan3: add inter-block offsets (inline reduce of 49 block sums) ----------------
__global__ void k_scan3() {
    __shared__ int s_w[2];
    __shared__ int s_off;
    int t = threadIdx.x;
    if (t < 64) {
        int v = (t < (int)blockIdx.x) ? g_bsum[t] : 0;   // blockIdx.x <= 48 < 64
#pragma unroll
        for (int off = 16; off; off >>= 1) v += __shfl_down_sync(0xffffffffu, v, off);
        if ((t & 31) == 0) s_w[t >> 5] = v;
    }
    __syncthreads();
    if (t == 0) s_off = s_w[0] + s_w[1];
    __syncthreads();
    int i = blockIdx.x * SCAN_B + t;
    if (i < N_NODES) {
        int rs = g_row_start[i] + s_off;
        g_row_start[i] = rs;
        g_cursor[i]    = rs;
    }
}

// ---------------- fill: 4 edges per thread for MLP ----------------
__global__ __launch_bounds__(256) void k_fill(const int* __restrict__ src, const int* __restrict__ dst) {
    int base = blockIdx.x * 1024 + threadIdx.x;
    int s[4], d[4];
    bool ok[4];
#pragma unroll
    for (int k = 0; k < 4; k++) {
        int e = base + k * 256;
        ok[k] = e < N_EDGES;
        s[k] = ok[k] ? src[e] : 0;
        d[k] = ok[k] ? dst[e] : 0;
    }
    int pos[4];
#pragma unroll
    for (int k = 0; k < 4; k++)
        if (ok[k]) pos[k] = atomicAdd(&g_cursor[clampi(d[k])], 1);
#pragma unroll
    for (int k = 0; k < 4; k++)
        if (ok[k]) g_csr_src[pos[k]] = clampi(s[k]);
}

// ---------------- gather1: h1 = fp16( relu( (sum no[s]*z1[s]) * ni + b1 ) * no ) ----------------
// one warp per node; lane owns 4 features (float4 from fp32 z1)
__global__ void k_gather1(const float* __restrict__ b1) {
    int warp = (blockIdx.x * blockDim.x + threadIdx.x) >> 5;
    int lane = threadIdx.x & 31;
    if (warp >= N_NODES) return;
    int start = g_row_start[warp];
    int end   = start + g_atomic[A_DEGI + warp];
    const float4* Z4 = (const float4*)g_z1f;
    float4 acc = make_float4(0.f, 0.f, 0.f, 0.f);
#pragma unroll 4
    for (int p = start; p < end; p++) {
        int s = __ldg(&g_csr_src[p]);
        float ns = __ldg(&g_norm_out[s]);          // warp-uniform broadcast
        float4 v = __ldg(&Z4[(size_t)s * 32 + lane]);
        acc.x = fmaf(v.x, ns, acc.x);
        acc.y = fmaf(v.y, ns, acc.y);
        acc.z = fmaf(v.z, ns, acc.z);
        acc.w = fmaf(v.w, ns, acc.w);
    }
    float ni = g_norm_in[warp];
    float no = g_norm_out[warp];
    float4 b = ((const float4*)b1)[lane];
    float4 o;
    o.x = fmaxf(fmaf(acc.x, ni, b.x), 0.f) * no;
    o.y = fmaxf(fmaf(acc.y, ni, b.y), 0.f) * no;
    o.z = fmaxf(fmaf(acc.z, ni, b.z), 0.f) * no;
    o.w = fmaxf(fmaf(acc.w, ni, b.w), 0.f) * no;
    __half2 h0 = __floats2half2_rn(o.x, o.y);
    __half2 h1v = __floats2half2_rn(o.z, o.w);
    uint2 u;
    u.x = *(uint32_t*)&h0; u.y = *(uint32_t*)&h1v;
    ((uint2*)g_h1h)[(size_t)warp * 32 + lane] = u;
}

// ---------------- tensor-core GEMM2: z2 = fp32( h1 @ W2 ) ----------------
__global__ __launch_bounds__(256) void k_gemm2(const __half* __restrict__ Xh,
                                               const float* __restrict__ W,
                                               float* __restrict__ Y) {
    constexpr int LDA = 136, LDB = 72;
    extern __shared__ __half sm[];
    __half* sA = sm;
    __half* sB = sm + 128 * LDA;

    int t = threadIdx.x;
    int row0 = blockIdx.x * 128;

    {
        int kq = t & 15;
        int rr = t >> 4;
        const uint4* X4 = (const uint4*)Xh;
#pragma unroll
        for (int p = 0; p < 8; p++) {
            int r  = rr + p * 16;
            int gr = min(row0 + r, N_NODES - 1);
            *(uint4*)(sA + r * LDA + kq * 8) = X4[(size_t)gr * 16 + kq];
        }
        int cq = t & 7;
        int r2 = t >> 3;
        const float4* W4 = (const float4*)W;
#pragma unroll
        for (int p = 0; p < 4; p++) {
            int r = r2 + p * 32;
            float4 v0 = W4[r * 16 + cq * 2];
            float4 v1 = W4[r * 16 + cq * 2 + 1];
            *(uint4*)(sB + r * LDB + cq * 8) = f8_to_h8(v0, v1);
        }
    }
    __syncthreads();

    int lane = t & 31;
    int wid  = t >> 5;
    int wm = wid >> 1;
    int wn = wid & 1;

    float acc[2][4][4];
#pragma unroll
    for (int i = 0; i < 2; i++)
#pragma unroll
        for (int j = 0; j < 4; j++)
#pragma unroll
            for (int q = 0; q < 4; q++) acc[i][j][q] = 0.f;

    uint32_t aaddr = s2u(sA) + (((wm * 32 + (lane & 15)) * LDA + (lane >> 4) * 8)) * 2;
    uint32_t baddr = s2u(sB) + ((((lane & 7) + ((lane >> 3) & 1) * 8) * LDB
                                 + wn * 32 + (lane >> 4) * 8)) * 2;

#pragma unroll
    for (int ks = 0; ks < 8; ks++) {
        uint32_t a[2][4];
        ldsm_x4(a[0][0], a[0][1], a[0][2], a[0][3], aaddr + ks * 32);
        ldsm_x4(a[1][0], a[1][1], a[1][2], a[1][3], aaddr + 16 * LDA * 2 + ks * 32);
        uint32_t b[4][2];
#pragma unroll
        for (int ntp = 0; ntp < 2; ntp++) {
            uint32_t r0, r1, r2, r3;
            ldsm_x4t(r0, r1, r2, r3, baddr + ks * 16 * LDB * 2 + ntp * 32);
            b[2 * ntp][0] = r0; b[2 * ntp][1] = r1;
            b[2 * ntp + 1][0] = r2; b[2 * ntp + 1][1] = r3;
        }
#pragma unroll
        for (int mt = 0; mt < 2; mt++)
#pragma unroll
            for (int nt = 0; nt < 4; nt++)
                mma16816(acc[mt][nt], a[mt], b[nt]);
    }

#pragma unroll
    for (int mt = 0; mt < 2; mt++) {
        int r1 = row0 + wm * 32 + mt * 16 + (lane >> 2);
#pragma unroll
        for (int nt = 0; nt < 4; nt++) {
            int c = wn * 32 + nt * 8 + ((lane & 3) << 1);
            if (r1 < N_NODES)
                *(float2*)(Y + (size_t)r1 * 64 + c)       = make_float2(acc[mt][nt][0], acc[mt][nt][1]);
            if (r1 + 8 < N_NODES)
                *(float2*)(Y + (size_t)(r1 + 8) * 64 + c) = make_float2(acc[mt][nt][2], acc[mt][nt][3]);
        }
    }
}

// ---------------- gather2: out = relu( (sum z2[src]) * norm_in + b2 ) ----------------
// one warp per node; lane owns 2 features (float2 from fp32 z2)
__global__ void k_gather2(const float* __restrict__ b2, float* __restrict__ out) {
    int warp = (blockIdx.x * blockDim.x + threadIdx.x) >> 5;
    int lane = threadIdx.x & 31;
    if (warp >= N_NODES) return;
    int start = g_row_start[warp];
    int end   = start + g_atomic[A_DEGI + warp];
    const float2* Z2 = (const float2*)g_z2f;
    float2 acc = make_float2(0.f, 0.f);
#pragma unroll 4
    for (int p = start; p < end; p++) {
        int s = __ldg(&g_csr_src[p]);
        float2 v = __ldg(&Z2[(size_t)s * 32 + lane]);
        acc.x += v.x; acc.y += v.y;
    }
    float ni = g_norm_in[warp];
    float2 b = ((const float2*)b2)[lane];
    float2 o;
    o.x = fmaxf(fmaf(acc.x, ni, b.x), 0.f);
    o.y = fmaxf(fmaf(acc.y, ni, b.y), 0.f);
    ((float2*)out)[(size_t)warp * 32 + lane] = o;
}

// ---------------- launch ----------------
extern "C" void kernel_launch(void* const* d_in, const int* in_sizes, int n_in,
                              void* d_out, int out_size) {
    const float* h   = (const float*)d_in[0];
    const float* W1  = (const float*)d_in[1];
    const float* b1  = (const float*)d_in[2];
    const float* W2  = (const float*)d_in[3];
    const float* b2  = (const float*)d_in[4];
    const int*   src = (const int*)d_in[5];   // JAX x64-disabled: int32
    const int*   dst = (const int*)d_in[6];
    float*       out = (float*)d_out;

    float *z1f, *z2f;
    __half* h1h;
    int* atom;
    cudaGetSymbolAddress((void**)&z1f,  g_z1f);
    cudaGetSymbolAddress((void**)&z2f,  g_z2f);
    cudaGetSymbolAddress((void**)&h1h,  g_h1h);
    cudaGetSymbolAddress((void**)&atom, g_atomic);

    const int SMEM1 = (128 * 136 + 128 * 136) * 2;   // 69632 B
    const int SMEM2 = (128 * 136 + 128 * 72) * 2;    // 53248 B
    cudaFuncSetAttribute((const void*)k_fusedA,
                         cudaFuncAttributeMaxDynamicSharedMemorySize, SMEM1);
    cudaFuncSetAttribute((const void*)k_gemm2,
                         cudaFuncAttributeMaxDynamicSharedMemorySize, SMEM2);

    const int T = 256;

    cudaMemsetAsync(atom, 0, A_TOTAL * sizeof(int));
    k_fusedA<<<GB1 + DEGB, T, SMEM1>>>(h, W1, z1f, src, dst);    // gemm1 || deg
    k_scan1 <<<SCAN_NB, SCAN_B>>>();                             // norms + block scans
    k_scan3 <<<SCAN_NB, SCAN_B>>>();                             // offsets + cursors
    k_fill  <<<(N_EDGES + 1023) / 1024, T>>>(src, dst);          // CSR fill (4 edges/thread)
    k_gather1<<<(N_NODES * 32 + T - 1) / T, T>>>(b1);
    k_gemm2 <<<GB1, T, SMEM2>>>(h1h, W2, z2f);
    k_gather2<<<(N_NODES * 32 + T - 1) / T, T>>>(b2, out);
}

// round 12
// speedup vs baseline: 1.8455x; 1.1765x over previous
#include <cuda_runtime.h>
#include <cuda_fp16.h>
#include <cstdint>

#define N_NODES 50000
#define N_EDGES 800000
#define F_IN    128
#define F_HID   128
#define F_OUT   64
#define SCAN_B  1024
#define SCAN_NB ((N_NODES + SCAN_B - 1) / SCAN_B)   // 49
#define GB1     ((N_NODES + 127) / 128)             // 391 gemm1 blocks
#define DEGB    ((N_EDGES + 255) / 256)             // 3125 deg blocks
#define FILLB   ((N_EDGES + 1023) / 1024)           // 782 fill blocks (4 edges/thread)

// ---- zero-init region (single memset): [0,N)=deg_out [N,2N)=deg_in ----
#define A_DEGO  0
#define A_DEGI  N_NODES
#define A_TOTAL (2 * N_NODES)
__device__ __align__(16) int    g_atomic[A_TOTAL];

__device__ __align__(16) __half g_z1h[N_NODES * F_HID];  // (h*norm_out)@W1      fp16 [N,128]
__device__ __align__(16) __half g_h1h[N_NODES * F_HID];  // relu layer1*norm_out fp16 [N,128]
__device__ __align__(16) __half g_z2h[N_NODES * F_OUT];  // h1@W2                fp16 [N,64]
__device__ __align__(16) float  g_norm_out[N_NODES];
__device__ __align__(16) float  g_norm_in [N_NODES];
__device__ __align__(16) int    g_row_start[N_NODES];
__device__ __align__(16) int    g_cursor[N_NODES];
__device__ __align__(16) int    g_bsum[64];
__device__ __align__(16) int    g_csr_src[N_EDGES];

__device__ __forceinline__ int clampi(int v) {
    return v < 0 ? 0 : (v >= N_NODES ? N_NODES - 1 : v);
}

__device__ __forceinline__ uint32_t s2u(const void* p) {
    uint32_t a;
    asm("{ .reg .u64 t; cvta.to.shared.u64 t, %1; cvt.u32.u64 %0, t; }" : "=r"(a) : "l"(p));
    return a;
}

__device__ __forceinline__ void ldsm_x4(uint32_t& r0, uint32_t& r1, uint32_t& r2, uint32_t& r3, uint32_t addr) {
    asm volatile("ldmatrix.sync.aligned.m8n8.x4.shared.b16 {%0,%1,%2,%3}, [%4];"
                 : "=r"(r0), "=r"(r1), "=r"(r2), "=r"(r3) : "r"(addr));
}

__device__ __forceinline__ void ldsm_x4t(uint32_t& r0, uint32_t& r1, uint32_t& r2, uint32_t& r3, uint32_t addr) {
    asm volatile("ldmatrix.sync.aligned.m8n8.x4.trans.shared.b16 {%0,%1,%2,%3}, [%4];"
                 : "=r"(r0), "=r"(r1), "=r"(r2), "=r"(r3) : "r"(addr));
}

__device__ __forceinline__ void mma16816(float* c, const uint32_t* a, const uint32_t* b) {
    asm volatile("mma.sync.aligned.m16n8k16.row.col.f32.f16.f16.f32 "
                 "{%0,%1,%2,%3}, {%4,%5,%6,%7}, {%8,%9}, {%0,%1,%2,%3};"
                 : "+f"(c[0]), "+f"(c[1]), "+f"(c[2]), "+f"(c[3])
                 : "r"(a[0]), "r"(a[1]), "r"(a[2]), "r"(a[3]), "r"(b[0]), "r"(b[1]));
}

__device__ __forceinline__ uint4 f8_to_h8(float4 v0, float4 v1, float s) {
    __half2 h0 = __floats2half2_rn(v0.x * s, v0.y * s);
    __half2 h1 = __floats2half2_rn(v0.z * s, v0.w * s);
    __half2 h2 = __floats2half2_rn(v1.x * s, v1.y * s);
    __half2 h3 = __floats2half2_rn(v1.z * s, v1.w * s);
    uint4 u;
    u.x = *(uint32_t*)&h0; u.y = *(uint32_t*)&h1;
    u.z = *(uint32_t*)&h2; u.w = *(uint32_t*)&h3;
    return u;
}

// ---------------- degree histogram ----------------
__global__ void k_deg(const int* __restrict__ src, const int* __restrict__ dst) {
    int e = blockIdx.x * blockDim.x + threadIdx.x;
    if (e < N_EDGES) {
        atomicAdd(&g_atomic[A_DEGO + clampi(src[e])], 1);
        atomicAdd(&g_atomic[A_DEGI + clampi(dst[e])], 1);
    }
}

// ---------------- scan1: block-local scan of deg_in + fused norms ----------------
__global__ void k_scan1() {
    __shared__ int wt[32];
    int i    = blockIdx.x * SCAN_B + threadIdx.x;
    int lane = threadIdx.x & 31;
    int wid  = threadIdx.x >> 5;
    int v = (i < N_NODES) ? g_atomic[A_DEGI + i] : 0;
    if (i < N_NODES) {
        g_norm_in [i] = rsqrtf((float)max(v, 1));
        g_norm_out[i] = rsqrtf((float)max(g_atomic[A_DEGO + i], 1));
    }
    int x = v;
#pragma unroll
    for (int off = 1; off < 32; off <<= 1) {
        int t = __shfl_up_sync(0xffffffffu, x, off);
        if (lane >= off) x += t;
    }
    if (lane == 31) wt[wid] = x;
    __syncthreads();
    if (wid == 0) {
        int y = wt[lane];
#pragma unroll
        for (int off = 1; off < 32; off <<= 1) {
            int t = __shfl_up_sync(0xffffffffu, y, off);
            if (lane >= off) y += t;
        }
        wt[lane] = y;
    }
    __syncthreads();
    if (wid > 0) x += wt[wid - 1];
    if (i < N_NODES) g_row_start[i] = x - v;
    if (threadIdx.x == SCAN_B - 1) g_bsum[blockIdx.x] = x;
}

// ---------------- scan3: add inter-block offsets (inline reduce of 49 block sums) ----------------
__global__ void k_scan3() {
    __shared__ int s_w[2];
    __shared__ int s_off;
    int t = threadIdx.x;
    if (t < 64) {
        int v = (t < (int)blockIdx.x) ? g_bsum[t] : 0;   // blockIdx.x <= 48 < 64
#pragma unroll
        for (int off = 16; off; off >>= 1) v += __shfl_down_sync(0xffffffffu, v, off);
        if ((t & 31) == 0) s_w[t >> 5] = v;
    }
    __syncthreads();
    if (t == 0) s_off = s_w[0] + s_w[1];
    __syncthreads();
    int i = blockIdx.x * SCAN_B + t;
    if (i < N_NODES) {
        int rs = g_row_start[i] + s_off;
        g_row_start[i] = rs;
        g_cursor[i]    = rs;
    }
}

// ======= fused C: blocks [0,GB1) = GEMM1 (z1 = fp16((h*norm_out)@W1));
//                  blocks [GB1,GB1+FILLB) = CSR fill (4 edges/thread).
// Both depend only on scan outputs (norms / cursors) — run concurrently. =======
__global__ __launch_bounds__(256) void k_fusedC(const float* __restrict__ X,
                                                const float* __restrict__ W,
                                                __half* __restrict__ Y,
                                                const int* __restrict__ src,
                                                const int* __restrict__ dst) {
    if (blockIdx.x >= GB1) {
        // ---- fill part ----
        int base = (blockIdx.x - GB1) * 1024 + threadIdx.x;
        int s[4], d[4];
        bool ok[4];
#pragma unroll
        for (int k = 0; k < 4; k++) {
            int e = base + k * 256;
            ok[k] = e < N_EDGES;
            s[k] = ok[k] ? src[e] : 0;
            d[k] = ok[k] ? dst[e] : 0;
        }
        int pos[4];
#pragma unroll
        for (int k = 0; k < 4; k++)
            if (ok[k]) pos[k] = atomicAdd(&g_cursor[clampi(d[k])], 1);
#pragma unroll
        for (int k = 0; k < 4; k++)
            if (ok[k]) g_csr_src[pos[k]] = clampi(s[k]);
        return;
    }

    // ---- GEMM1 part: 128x128x128, 8 warps ----
    constexpr int LDA = 136, LDB = 136;
    extern __shared__ __half sm[];
    __half* sA = sm;
    __half* sB = sm + 128 * LDA;

    int t = threadIdx.x;
    int row0 = blockIdx.x * 128;

    {
        int kq = t & 15;
        int rr = t >> 4;
        const float4* X4 = (const float4*)X;
        const float4* W4 = (const float4*)W;
#pragma unroll
        for (int p = 0; p < 8; p++) {
            int r  = rr + p * 16;
            int gr = min(row0 + r, N_NODES - 1);
            float no = g_norm_out[gr];
            float4 v0 = X4[(size_t)gr * 32 + kq * 2];
            float4 v1 = X4[(size_t)gr * 32 + kq * 2 + 1];
            *(uint4*)(sA + r * LDA + kq * 8) = f8_to_h8(v0, v1, no);
        }
#pragma unroll
        for (int p = 0; p < 8; p++) {
            int r = rr + p * 16;
            float4 v0 = W4[r * 32 + kq * 2];
            float4 v1 = W4[r * 32 + kq * 2 + 1];
            *(uint4*)(sB + r * LDB + kq * 8) = f8_to_h8(v0, v1, 1.0f);
        }
    }
    __syncthreads();

    int lane = t & 31;
    int wid  = t >> 5;
    int wm = wid >> 1;
    int wn = wid & 1;

    float acc[2][8][4];
#pragma unroll
    for (int i = 0; i < 2; i++)
#pragma unroll
        for (int j = 0; j < 8; j++)
#pragma unroll
            for (int q = 0; q < 4; q++) acc[i][j][q] = 0.f;

    uint32_t aaddr = s2u(sA) + (((wm * 32 + (lane & 15)) * LDA + (lane >> 4) * 8)) * 2;
    uint32_t baddr = s2u(sB) + ((((lane & 7) + ((lane >> 3) & 1) * 8) * LDB
                                 + wn * 64 + (lane >> 4) * 8)) * 2;

#pragma unroll
    for (int ks = 0; ks < 8; ks++) {
        uint32_t a[2][4];
        ldsm_x4(a[0][0], a[0][1], a[0][2], a[0][3], aaddr + ks * 32);
        ldsm_x4(a[1][0], a[1][1], a[1][2], a[1][3], aaddr + 16 * LDA * 2 + ks * 32);
        uint32_t b[8][2];
#pragma unroll
        for (int ntp = 0; ntp < 4; ntp++) {
            uint32_t r0, r1, r2, r3;
            ldsm_x4t(r0, r1, r2, r3, baddr + ks * 16 * LDB * 2 + ntp * 32);
            b[2 * ntp][0] = r0; b[2 * ntp][1] = r1;
            b[2 * ntp + 1][0] = r2; b[2 * ntp + 1][1] = r3;
        }
#pragma unroll
        for (int mt = 0; mt < 2; mt++)
#pragma unroll
            for (int nt = 0; nt < 8; nt++)
                mma16816(acc[mt][nt], a[mt], b[nt]);
    }

#pragma unroll
    for (int mt = 0; mt < 2; mt++) {
        int r1 = row0 + wm * 32 + mt * 16 + (lane >> 2);
#pragma unroll
        for (int nt = 0; nt < 8; nt++) {
            int c = wn * 64 + nt * 8 + ((lane & 3) << 1);
            __half2 lo = __floats2half2_rn(acc[mt][nt][0], acc[mt][nt][1]);
            __half2 hi = __floats2half2_rn(acc[mt][nt][2], acc[mt][nt][3]);
            if (r1 < N_NODES)     *(__half2*)(Y + (size_t)r1 * 128 + c)       = lo;
            if (r1 + 8 < N_NODES) *(__half2*)(Y + (size_t)(r1 + 8) * 128 + c) = hi;
        }
    }
}

// ---------------- gather1: h1 = fp16( relu( (sum z1[s]) * ni + b1 ) * no ) ----------------
// z1 rows already scaled by norm_out[src] (folded into GEMM1).
// one warp per node; lane owns 4 features (uint2 = 2 half2)
__global__ void k_gather1(const float* __restrict__ b1) {
    int warp = (blockIdx.x * blockDim.x + threadIdx.x) >> 5;
    int lane = threadIdx.x & 31;
    if (warp >= N_NODES) return;
    int start = g_row_start[warp];
    int end   = start + g_atomic[A_DEGI + warp];
    const uint2* Z2 = (const uint2*)g_z1h;
    float4 acc = make_float4(0.f, 0.f, 0.f, 0.f);
#pragma unroll 4
    for (int p = start; p < end; p++) {
        int s = __ldg(&g_csr_src[p]);
        uint2 v = __ldg(&Z2[(size_t)s * 32 + lane]);
        float2 f0 = __half22float2(*(__half2*)&v.x);
        float2 f1 = __half22float2(*(__half2*)&v.y);
        acc.x += f0.x; acc.y += f0.y; acc.z += f1.x; acc.w += f1.y;
    }
    float ni = g_norm_in[warp];
    float no = g_norm_out[warp];
    float4 b = ((const float4*)b1)[lane];
    float4 o;
    o.x = fmaxf(fmaf(acc.x, ni, b.x), 0.f) * no;
    o.y = fmaxf(fmaf(acc.y, ni, b.y), 0.f) * no;
    o.z = fmaxf(fmaf(acc.z, ni, b.z), 0.f) * no;
    o.w = fmaxf(fmaf(acc.w, ni, b.w), 0.f) * no;
    __half2 h0 = __floats2half2_rn(o.x, o.y);
    __half2 h1v = __floats2half2_rn(o.z, o.w);
    uint2 u;
    u.x = *(uint32_t*)&h0; u.y = *(uint32_t*)&h1v;
    ((uint2*)g_h1h)[(size_t)warp * 32 + lane] = u;
}

// ---------------- tensor-core GEMM2: z2 = fp16( h1 @ W2 ) ----------------
__global__ __launch_bounds__(256) void k_gemm2(const __half* __restrict__ Xh,
                                               const float* __restrict__ W,
                                               __half* __restrict__ Y) {
    constexpr int LDA = 136, LDB = 72;
    extern __shared__ __half sm[];
    __half* sA = sm;
    __half* sB = sm + 128 * LDA;

    int t = threadIdx.x;
    int row0 = blockIdx.x * 128;

    {
        int kq = t & 15;
        int rr = t >> 4;
        const uint4* X4 = (const uint4*)Xh;
#pragma unroll
        for (int p = 0; p < 8; p++) {
            int r  = rr + p * 16;
            int gr = min(row0 + r, N_NODES - 1);
            *(uint4*)(sA + r * LDA + kq * 8) = X4[(size_t)gr * 16 + kq];
        }
        int cq = t & 7;
        int r2 = t >> 3;
        const float4* W4 = (const float4*)W;
#pragma unroll
        for (int p = 0; p < 4; p++) {
            int r = r2 + p * 32;
            float4 v0 = W4[r * 16 + cq * 2];
            float4 v1 = W4[r * 16 + cq * 2 + 1];
            *(uint4*)(sB + r * LDB + cq * 8) = f8_to_h8(v0, v1, 1.0f);
        }
    }
    __syncthreads();

    int lane = t & 31;
    int wid  = t >> 5;
    int wm = wid >> 1;
    int wn = wid & 1;

    float acc[2][4][4];
#pragma unroll
    for (int i = 0; i < 2; i++)
#pragma unroll
        for (int j = 0; j < 4; j++)
#pragma unroll
            for (int q = 0; q < 4; q++) acc[i][j][q] = 0.f;

    uint32_t aaddr = s2u(sA) + (((wm * 32 + (lane & 15)) * LDA + (lane >> 4) * 8)) * 2;
    uint32_t baddr = s2u(sB) + ((((lane & 7) + ((lane >> 3) & 1) * 8) * LDB
                                 + wn * 32 + (lane >> 4) * 8)) * 2;

#pragma unroll
    for (int ks = 0; ks < 8; ks++) {
        uint32_t a[2][4];
        ldsm_x4(a[0][0], a[0][1], a[0][2], a[0][3], aaddr + ks * 32);
        ldsm_x4(a[1][0], a[1][1], a[1][2], a[1][3], aaddr + 16 * LDA * 2 + ks * 32);
        uint32_t b[4][2];
#pragma unroll
        for (int ntp = 0; ntp < 2; ntp++) {
            uint32_t r0, r1, r2, r3;
            ldsm_x4t(r0, r1, r2, r3, baddr + ks * 16 * LDB * 2 + ntp * 32);
            b[2 * ntp][0] = r0; b[2 * ntp][1] = r1;
            b[2 * ntp + 1][0] = r2; b[2 * ntp + 1][1] = r3;
        }
#pragma unroll
        for (int mt = 0; mt < 2; mt++)
#pragma unroll
            for (int nt = 0; nt < 4; nt++)
                mma16816(acc[mt][nt], a[mt], b[nt]);
    }

#pragma unroll
    for (int mt = 0; mt < 2; mt++) {
        int r1 = row0 + wm * 32 + mt * 16 + (lane >> 2);
#pragma unroll
        for (int nt = 0; nt < 4; nt++) {
            int c = wn * 32 + nt * 8 + ((lane & 3) << 1);
            __half2 lo = __floats2half2_rn(acc[mt][nt][0], acc[mt][nt][1]);
            __half2 hi = __floats2half2_rn(acc[mt][nt][2], acc[mt][nt][3]);
            if (r1 < N_NODES)     *(__half2*)(Y + (size_t)r1 * 64 + c)       = lo;
            if (r1 + 8 < N_NODES) *(__half2*)(Y + (size_t)(r1 + 8) * 64 + c) = hi;
        }
    }
}

// ---------------- gather2: out = relu( (sum z2[src]) * norm_in + b2 ) ----------------
__global__ void k_gather2(const float* __restrict__ b2, float* __restrict__ out) {
    int warp = (blockIdx.x * blockDim.x + threadIdx.x) >> 5;
    int lane = threadIdx.x & 31;
    if (warp >= N_NODES) return;
    int start = g_row_start[warp];
    int end   = start + g_atomic[A_DEGI + warp];
    const uint32_t* Y1 = (const uint32_t*)g_z2h;
    float2 acc = make_float2(0.f, 0.f);
#pragma unroll 4
    for (int p = start; p < end; p++) {
        int s = __ldg(&g_csr_src[p]);
        uint32_t v = __ldg(&Y1[(size_t)s * 32 + lane]);
        float2 f = __half22float2(*(__half2*)&v);
        acc.x += f.x; acc.y += f.y;
    }
    float ni = g_norm_in[warp];
    float2 b = ((const float2*)b2)[lane];
    float2 o;
    o.x = fmaxf(fmaf(acc.x, ni, b.x), 0.f);
    o.y = fmaxf(fmaf(acc.y, ni, b.y), 0.f);
    ((float2*)out)[(size_t)warp * 32 + lane] = o;
}

// ---------------- launch ----------------
extern "C" void kernel_launch(void* const* d_in, const int* in_sizes, int n_in,
                              void* d_out, int out_size) {
    const float* h   = (const float*)d_in[0];
    const float* W1  = (const float*)d_in[1];
    const float* b1  = (const float*)d_in[2];
    const float* W2  = (const float*)d_in[3];
    const float* b2  = (const float*)d_in[4];
    const int*   src = (const int*)d_in[5];   // JAX x64-disabled: int32
    const int*   dst = (const int*)d_in[6];
    float*       out = (float*)d_out;

    __half *z1h, *h1h, *z2h;
    int* atom;
    cudaGetSymbolAddress((void**)&z1h,  g_z1h);
    cudaGetSymbolAddress((void**)&h1h,  g_h1h);
    cudaGetSymbolAddress((void**)&z2h,  g_z2h);
    cudaGetSymbolAddress((void**)&atom, g_atomic);

    const int SMEM1 = (128 * 136 + 128 * 136) * 2;   // 69632 B
    const int SMEM2 = (128 * 136 + 128 * 72) * 2;    // 53248 B
    cudaFuncSetAttribute((const void*)k_fusedC,
                         cudaFuncAttributeMaxDynamicSharedMemorySize, SMEM1);
    cudaFuncSetAttribute((const void*)k_gemm2,
                         cudaFuncAttributeMaxDynamicSharedMemorySize, SMEM2);

    const int T = 256;

    cudaMemsetAsync(atom, 0, A_TOTAL * sizeof(int));
    k_deg   <<<DEGB, T>>>(src, dst);                            // degrees
    k_scan1 <<<SCAN_NB, SCAN_B>>>();                            // norms + block scans
    k_scan3 <<<SCAN_NB, SCAN_B>>>();                            // offsets + cursors
    k_fusedC<<<GB1 + FILLB, T, SMEM1>>>(h, W1, z1h, src, dst);  // gemm1(norm-scaled) || CSR fill
    k_gather1<<<(N_NODES * 32 + T - 1) / T, T>>>(b1);
    k_gemm2 <<<GB1, T, SMEM2>>>(h1h, W2, z2h);
    k_gather2<<<(N_NODES * 32 + T - 1) / T, T>>>(b2, out);
}